// round 4
// baseline (speedup 1.0000x reference)
#include <cuda_runtime.h>
#include <math.h>

// SphereConv: out[2,B,F,L,M] from x[B,1,C,L,M] (complex as 2 arrays) and
// w[F,C,N,1] (complex), weights linearly interpolated N=64 -> L=256 along l,
// channel-mean, sqrt(1+l) scale, relu on real part.
//
// R3: kernel is FFMA-issue-bound (3-reg FFMA rt_SMSP=2). Switch the inner
// product to packed fma.rn.f32x2 (2 FMA/issue). Weights pre-duplicated in
// shared as (w,w) pairs so packed operands come straight from LDS.128.
namespace {

constexpr int B = 4, C = 32, L = 256, M = 256, F = 8, N = 64;
constexpr int FG = 2;                 // f-groups per block
constexpr int FPT = F / FG;           // filters per thread = 4
constexpr int THREADS = 64 * FG;      // 128
constexpr int CSTRIDE2 = L * M / 4;   // stride between channels in 16B units

__device__ __forceinline__ unsigned long long fma2(unsigned long long a,
                                                   unsigned long long b,
                                                   unsigned long long c)
{
    unsigned long long d;
    asm("fma.rn.f32x2 %0, %1, %2, %3;" : "=l"(d) : "l"(a), "l"(b), "l"(c));
    return d;
}

__device__ __forceinline__ float lo32(unsigned long long v)
{
    return __uint_as_float((unsigned int)v);
}
__device__ __forceinline__ float hi32(unsigned long long v)
{
    return __uint_as_float((unsigned int)(v >> 32));
}

__global__ __launch_bounds__(THREADS)
void sphere_conv_kernel(const float* __restrict__ xr,
                        const float* __restrict__ xi,
                        const float* __restrict__ wr,
                        const float* __restrict__ wi,
                        float* __restrict__ out)
{
    const int bl = blockIdx.x;
    const int b  = bl >> 8;        // bl / L
    const int l  = bl & (L - 1);   // bl % L

    // Interpolated, pre-duplicated weights: [c][f] layout, f fast (8 per c).
    // wA = (a,a), wB = (b,b), wN = (-b,-b) where (a + i b) is the weight.
    __shared__ float2 wA[C * F];
    __shared__ float2 wB[C * F];
    __shared__ float2 wN[C * F];

    const int tid = threadIdx.x;
    const int fg  = tid >> 6;      // f-group (0/1)
    const int m4  = tid & 63;      // 16B-chunk index within the M=256 row

    {
        float t  = ((float)l / (float)(L - 1)) * (float)(N - 1);
        int   lo = (int)floorf(t);
        lo = lo < 0 ? 0 : (lo > N - 2 ? N - 2 : lo);
        float frac = t - (float)lo;
        float sc = sqrtf(1.0f + (float)l) * (1.0f / (float)C);
        for (int i = tid; i < C * F; i += THREADS) {
            int c = i >> 3;   // i / F
            int f = i & 7;    // i % F
            int widx = (f * C + c) * N + lo;
            float a  = (wr[widx] * (1.0f - frac) + wr[widx + 1] * frac) * sc;
            float bb = (wi[widx] * (1.0f - frac) + wi[widx + 1] * frac) * sc;
            wA[i] = make_float2(a, a);
            wB[i] = make_float2(bb, bb);
            wN[i] = make_float2(-bb, -bb);
        }
    }
    __syncthreads();

    const size_t base = ((size_t)b * C * L + l) * (M / 4) + m4;
    const ulonglong2* xr2 = reinterpret_cast<const ulonglong2*>(xr) + base;
    const ulonglong2* xi2 = reinterpret_cast<const ulonglong2*>(xi) + base;

    // Packed accumulators: per filter, 2 f32x2 for real, 2 for imag.
    unsigned long long ar0[FPT], ar1[FPT], ai0[FPT], ai1[FPT];
#pragma unroll
    for (int f = 0; f < FPT; ++f) {
        ar0[f] = 0ull; ar1[f] = 0ull; ai0[f] = 0ull; ai1[f] = 0ull;
    }

    // ull2 view of the weight arrays: index c*4 + fg*2 + {0,1} covers this
    // group's 4 filters, two packed weights per LDS.128.
    const ulonglong2* A2 = reinterpret_cast<const ulonglong2*>(wA);
    const ulonglong2* B2 = reinterpret_cast<const ulonglong2*>(wB);
    const ulonglong2* N2 = reinterpret_cast<const ulonglong2*>(wN);
    const int woff = fg * 2;

#pragma unroll 8
    for (int c = 0; c < C; ++c) {
        ulonglong2 vr = xr2[c * CSTRIDE2];   // (m0,m1) , (m2,m3)
        ulonglong2 vi = xi2[c * CSTRIDE2];
        int wb = c * 4 + woff;
        ulonglong2 a01 = A2[wb], a23 = A2[wb + 1];
        ulonglong2 b01 = B2[wb], b23 = B2[wb + 1];
        ulonglong2 n01 = N2[wb], n23 = N2[wb + 1];

        unsigned long long aw[FPT] = {a01.x, a01.y, a23.x, a23.y};
        unsigned long long bw[FPT] = {b01.x, b01.y, b23.x, b23.y};
        unsigned long long nw[FPT] = {n01.x, n01.y, n23.x, n23.y};

#pragma unroll
        for (int f = 0; f < FPT; ++f) {
            // real: += a*xr - b*xi ; imag: += a*xi + b*xr  (packed over 2 m's)
            ar0[f] = fma2(aw[f], vr.x, fma2(nw[f], vi.x, ar0[f]));
            ar1[f] = fma2(aw[f], vr.y, fma2(nw[f], vi.y, ar1[f]));
            ai0[f] = fma2(aw[f], vi.x, fma2(bw[f], vr.x, ai0[f]));
            ai1[f] = fma2(aw[f], vi.y, fma2(bw[f], vr.y, ai1[f]));
        }
    }

    // out shape (2, B, F, L, M); real part gets relu.
    float4* out4 = reinterpret_cast<float4*>(out);
    ulonglong2* outu = reinterpret_cast<ulonglong2*>(out);
#pragma unroll
    for (int f = 0; f < FPT; ++f) {
        int fglob = fg * FPT + f;
        float4 r;
        r.x = fmaxf(lo32(ar0[f]), 0.f);
        r.y = fmaxf(hi32(ar0[f]), 0.f);
        r.z = fmaxf(lo32(ar1[f]), 0.f);
        r.w = fmaxf(hi32(ar1[f]), 0.f);
        size_t or4 = (((size_t)(0 * B + b) * F + fglob) * L + l) * (M / 4) + m4;
        size_t oi4 = (((size_t)(1 * B + b) * F + fglob) * L + l) * (M / 4) + m4;
        out4[or4] = r;
        ulonglong2 iv;
        iv.x = ai0[f];
        iv.y = ai1[f];
        outu[oi4] = iv;
    }
}

}  // namespace

extern "C" void kernel_launch(void* const* d_in, const int* in_sizes, int n_in,
                              void* d_out, int out_size)
{
    const float* xr = (const float*)d_in[0];
    const float* xi = (const float*)d_in[1];
    const float* wr = (const float*)d_in[2];
    const float* wi = (const float*)d_in[3];
    float* out = (float*)d_out;
    sphere_conv_kernel<<<B * L, THREADS>>>(xr, xi, wr, wi, out);
}